// round 13
// baseline (speedup 1.0000x reference)
#include <cuda_runtime.h>
#include <cuda_bf16.h>
#include <cuda_fp16.h>
#include <cstdint>

#define BATCH 4
#define CIN   256
#define COUT  128
#define NTOK  4096

// ---------------------------------------------------------------------------
// Scratch (__device__ globals; allocation-free rule)
// Packed layouts so one GEMM launch covers q AND k:
//   g_x_*  : z in [0,4) = p^T [b][n][c], z in [4,8) = b^T [b][n][c]
//   g_w_*  : [0,COUT*CIN) = Wq, [COUT*CIN, 2*COUT*CIN) = Wk
//   g_bias2: [0,COUT) = bq, [COUT,2*COUT) = bk
//   g_qk_* : z in [0,4) = q [b][n][o], z in [4,8) = k [b][m][o]
// ---------------------------------------------------------------------------
__device__ __nv_bfloat16 g_x_hi [(long long)2 * BATCH * NTOK * CIN];
__device__ __nv_bfloat16 g_x_lo [(long long)2 * BATCH * NTOK * CIN];
__device__ __nv_bfloat16 g_w_hi [2 * COUT * CIN];
__device__ __nv_bfloat16 g_w_lo [2 * COUT * CIN];
__device__ float         g_bias2[2 * COUT];
__device__ __nv_bfloat16 g_qk_hi[(long long)2 * BATCH * NTOK * COUT];
__device__ __nv_bfloat16 g_qk_lo[(long long)2 * BATCH * NTOK * COUT];
__device__ float         g_att  [(long long)BATCH * NTOK * NTOK];   // fp32 logits
__device__ __half        g_ph   [(long long)BATCH * NTOK * NTOK];   // softmax fp16
__device__ __half        g_vh   [(long long)BATCH * CIN * NTOK];    // V fp16 [b][c][m]

// ---------------------------------------------------------------------------
// Streams/events for per-batch pipeline overlap (created in static init;
// fork/join via events is stream-capture legal).
// ---------------------------------------------------------------------------
struct GpuSideStreams {
    cudaStream_t s[BATCH - 1];
    cudaEvent_t  root;
    cudaEvent_t  done[BATCH - 1];
    bool ok;
    GpuSideStreams() : ok(true) {
        for (int i = 0; i < BATCH - 1; i++)
            ok &= (cudaStreamCreateWithFlags(&s[i], cudaStreamNonBlocking) == cudaSuccess);
        ok &= (cudaEventCreateWithFlags(&root, cudaEventDisableTiming) == cudaSuccess);
        for (int i = 0; i < BATCH - 1; i++)
            ok &= (cudaEventCreateWithFlags(&done[i], cudaEventDisableTiming) == cudaSuccess);
    }
};
static GpuSideStreams g_ss;

// ---------------------------------------------------------------------------
// Helpers (plain sm_80+ PTX; toolchain targets compute_103 — no tcgen05)
// ---------------------------------------------------------------------------
__device__ __forceinline__ uint32_t smem_u32(const void* p) {
    uint32_t a;
    asm("{ .reg .u64 t; cvta.to.shared.u64 t, %1; cvt.u32.u64 %0, t; }"
        : "=r"(a) : "l"(p));
    return a;
}
__device__ __forceinline__ void cp16(uint32_t dst, const void* src) {
    asm volatile("cp.async.cg.shared.global [%0], [%1], 16;"
                 :: "r"(dst), "l"(src) : "memory");
}
__device__ __forceinline__ void cp_commit() {
    asm volatile("cp.async.commit_group;" ::: "memory");
}
template<int N>
__device__ __forceinline__ void cp_wait() {
    asm volatile("cp.async.wait_group %0;" :: "n"(N) : "memory");
}
__device__ __forceinline__ void ldsm4(uint32_t* r, uint32_t addr) {
    asm volatile("ldmatrix.sync.aligned.m8n8.x4.shared.b16 {%0,%1,%2,%3}, [%4];"
                 : "=r"(r[0]), "=r"(r[1]), "=r"(r[2]), "=r"(r[3]) : "r"(addr));
}
// FMT 0 = bf16, FMT 1 = fp16 (same fragment layout, different instruction)
template<int FMT>
__device__ __forceinline__ void hmma(float* c, const uint32_t* a, const uint32_t* b) {
    if (FMT == 0)
        asm volatile(
            "mma.sync.aligned.m16n8k16.row.col.f32.bf16.bf16.f32 "
            "{%0,%1,%2,%3}, {%4,%5,%6,%7}, {%8,%9}, {%0,%1,%2,%3};"
            : "+f"(c[0]), "+f"(c[1]), "+f"(c[2]), "+f"(c[3])
            : "r"(a[0]), "r"(a[1]), "r"(a[2]), "r"(a[3]), "r"(b[0]), "r"(b[1]));
    else
        asm volatile(
            "mma.sync.aligned.m16n8k16.row.col.f32.f16.f16.f32 "
            "{%0,%1,%2,%3}, {%4,%5,%6,%7}, {%8,%9}, {%0,%1,%2,%3};"
            : "+f"(c[0]), "+f"(c[1]), "+f"(c[2]), "+f"(c[3])
            : "r"(a[0]), "r"(a[1]), "r"(a[2]), "r"(a[3]), "r"(b[0]), "r"(b[1]));
}
__device__ __forceinline__ void split2(float x, __nv_bfloat16& h, __nv_bfloat16& l) {
    h = __float2bfloat16(x);
    l = __float2bfloat16(x - __bfloat162float(h));
}

// ---------------------------------------------------------------------------
// Fused prep (single launch):
//  z in [0,BATCH):        p [c][n] -> x hi/lo [z][n][c] (bf16)
//  z in [BATCH,2*BATCH):  b [c][n] -> x hi/lo [z][n][c] (bf16) AND V fp16 [c][n]
//  z == 2*BATCH:          Wq|Wk elementwise bf16 split + bias pack
// ---------------------------------------------------------------------------
__global__ __launch_bounds__(256)
void prep_all(const float* __restrict__ p, const float* __restrict__ bsrc,
              const float* __restrict__ Wq, const float* __restrict__ Wk,
              const float* __restrict__ bq, const float* __restrict__ bk,
              __nv_bfloat16* __restrict__ x_hi, __nv_bfloat16* __restrict__ x_lo,
              __half* __restrict__ vh,
              __nv_bfloat16* __restrict__ w_hi, __nv_bfloat16* __restrict__ w_lo,
              float* __restrict__ bias2)
{
    const int z = blockIdx.z;
    const int tx = threadIdx.x, ty = threadIdx.y;
    const int tid = ty * 32 + tx;

    if (z == 2 * BATCH) {
        int idx = (blockIdx.y * gridDim.x + blockIdx.x) * 256 + tid;
        if (idx < 2 * COUT * CIN) {
            float v = (idx < COUT * CIN) ? Wq[idx] : Wk[idx - COUT * CIN];
            split2(v, w_hi[idx], w_lo[idx]);
        }
        if (blockIdx.x == 0 && blockIdx.y == 0)
            bias2[tid] = (tid < COUT) ? bq[tid] : bk[tid - COUT];
        return;
    }

    const bool isB = (z >= BATCH);
    const int  zb  = isB ? z - BATCH : z;
    const float* in = isB ? bsrc : p;

    __shared__ float t[32][33];
    const long long zin  = (long long)zb * CIN * NTOK;
    const long long zout = (long long)z  * NTOK * CIN;
    const int n0 = blockIdx.x * 32, c0 = blockIdx.y * 32;

#pragma unroll
    for (int j = 0; j < 32; j += 8) {
        const long long src = zin + (long long)(c0 + ty + j) * NTOK + n0 + tx;
        float v = in[src];
        t[ty + j][tx] = v;
        if (isB) vh[src] = __float2half_rn(v);
    }
    __syncthreads();
#pragma unroll
    for (int j = 0; j < 32; j += 8) {
        float v = t[tx][ty + j];
        __nv_bfloat16 h, l;
        split2(v, h, l);
        long long o = zout + (long long)(n0 + ty + j) * CIN + c0 + tx;
        x_hi[o] = h; x_lo[o] = l;
    }
}

// ---------------------------------------------------------------------------
// Softmax over rows of att; writes single fp16 probs
// ---------------------------------------------------------------------------
__device__ __forceinline__ float warp_max(float x) {
#pragma unroll
    for (int o = 16; o > 0; o >>= 1) x = fmaxf(x, __shfl_xor_sync(0xffffffffu, x, o));
    return x;
}
__device__ __forceinline__ float warp_sum(float x) {
#pragma unroll
    for (int o = 16; o > 0; o >>= 1) x += __shfl_xor_sync(0xffffffffu, x, o);
    return x;
}

__global__ __launch_bounds__(256)
void softmax_fp16(const float* __restrict__ att, __half* __restrict__ ph) {
    const long long ro = (long long)blockIdx.x * NTOK;
    const float* row = att + ro;
    const int tid = threadIdx.x;

    float4 v[4];
    float m = -1e30f;
#pragma unroll
    for (int i = 0; i < 4; i++) {
        v[i] = *(const float4*)(row + i * 1024 + tid * 4);
        m = fmaxf(m, fmaxf(fmaxf(v[i].x, v[i].y), fmaxf(v[i].z, v[i].w)));
    }
    __shared__ float sred[8];
    m = warp_max(m);
    if ((tid & 31) == 0) sred[tid >> 5] = m;
    __syncthreads();
    {
        float t = (tid < 8) ? sred[tid & 7] : -1e30f;
        t = warp_max(t);
        if (tid == 0) sred[0] = t;
    }
    __syncthreads();
    m = sred[0];

    float s = 0.f;
#pragma unroll
    for (int i = 0; i < 4; i++) {
        v[i].x = __expf(v[i].x - m); v[i].y = __expf(v[i].y - m);
        v[i].z = __expf(v[i].z - m); v[i].w = __expf(v[i].w - m);
        s += v[i].x + v[i].y + v[i].z + v[i].w;
    }
    s = warp_sum(s);
    __syncthreads();
    if ((tid & 31) == 0) sred[tid >> 5] = s;
    __syncthreads();
    {
        float t = (tid < 8) ? sred[tid & 7] : 0.f;
        t = warp_sum(t);
        if (tid == 0) sred[0] = t;
    }
    __syncthreads();
    const float inv = 1.f / sred[0];

#pragma unroll
    for (int i = 0; i < 4; i++) {
        long long off = ro + i * 1024 + tid * 4;
        ((__half2*)(ph + off))[0] =
            __floats2half2_rn(v[i].x * inv, v[i].y * inv);
        ((__half2*)(ph + off))[1] =
            __floats2half2_rn(v[i].z * inv, v[i].w * inv);
    }
}

// ---------------------------------------------------------------------------
// Split-precision HMMA GEMM:  C[m][n] = sum_k A(m,k)*B(n,k), A/B K-major.
// Products: ah*bh  (+ ah*bl if SPLITB)  (+ al*bh if SPLITA)
// OCC   = min blocks/SM for launch_bounds
// ZDIVB = B (and bias) advance by z/ZDIVB (one launch covers Wq and Wk)
// EPI 0: Cf[m*ldC + n] fp32   EPI 1: Chi/Clo +bias   EPI 2: Cf[n*ldC+m] staged
// NOTE: dynamic smem must be >= max(STAGES*STG, EPI2 tile (BM+4)*BN*4).
// ---------------------------------------------------------------------------
#define KSLAB 32
#define RSTRB 80   // smem row stride bytes (32 elems + 16B pad, conflict-free)

template<int FMT, int BM, int BN, int WM, int WN, bool SPLITA, bool SPLITB,
         int EPI, int STAGES, int OCC, int ZDIVB>
__global__ __launch_bounds__(WM * WN * 32, OCC)
void gemm_mma(const uint16_t* __restrict__ Ah, const uint16_t* __restrict__ Al,
              const uint16_t* __restrict__ Bh, const uint16_t* __restrict__ Bl,
              const float* __restrict__ bias,
              float* __restrict__ Cf,
              __nv_bfloat16* __restrict__ Chi, __nv_bfloat16* __restrict__ Clo,
              int K, long long sA, long long sB, long long sC, int ldC)
{
    constexpr int THREADS = WM * WN * 32;
    constexpr int MT   = BM / WM / 16;
    constexpr int NT8  = BN / WN / 8;
    constexpr int ASZA = BM * RSTRB;
    constexpr int ASZB = BN * RSTRB;
    constexpr int NA   = SPLITA ? 2 : 1;
    constexpr int NB   = SPLITB ? 2 : 1;
    constexpr int STG  = NA * ASZA + NB * ASZB;

    extern __shared__ char smem[];
    const uint32_t sb = smem_u32(smem);
    const int tid = threadIdx.x, warp = tid >> 5, lane = tid & 31;
    const int wm = warp % WM, wn = warp / WM;
    const int m0 = blockIdx.x * BM;
    const int n0 = blockIdx.y * BN;
    const int z  = blockIdx.z;
    const int zb = z / ZDIVB;

    Ah += (long long)z * sA + (long long)m0 * K;
    if (SPLITA) Al += (long long)z * sA + (long long)m0 * K;
    Bh += (long long)zb * sB + (long long)n0 * K;
    if (SPLITB) Bl += (long long)zb * sB + (long long)n0 * K;
    if (EPI == 0 || EPI == 2) Cf += (long long)z * sC;
    else { Chi += (long long)z * sC; Clo += (long long)z * sC; bias += (long long)zb * ldC; }

    float acc[MT][NT8][4];
#pragma unroll
    for (int i = 0; i < MT; i++)
#pragma unroll
        for (int j = 0; j < NT8; j++)
#pragma unroll
            for (int r = 0; r < 4; r++) acc[i][j][r] = 0.f;

    auto load_slab = [&](int s, int b) {
        const uint32_t base = sb + (uint32_t)b * STG;
        const long long kof = (long long)s * KSLAB;
#pragma unroll
        for (int i = 0; i < BM * 4 / THREADS; i++) {
            const int id = tid + i * THREADS;
            const int r = id >> 2, g = id & 3;
            const uint32_t so = base + (uint32_t)(r * RSTRB + g * 16);
            const long long go = (long long)r * K + kof + g * 8;
            cp16(so, Ah + go);
            if (SPLITA) cp16(so + ASZA, Al + go);
        }
        const uint32_t bbase = base + NA * ASZA;
#pragma unroll
        for (int i = 0; i < BN * 4 / THREADS; i++) {
            const int id = tid + i * THREADS;
            const int r = id >> 2, g = id & 3;
            const uint32_t so = bbase + (uint32_t)(r * RSTRB + g * 16);
            const long long go = (long long)r * K + kof + g * 8;
            cp16(so, Bh + go);
            if (SPLITB) cp16(so + ASZB, Bl + go);
        }
    };

    const int arow = (lane & 7) + ((lane >> 3) & 1) * 8;
    const int akof = (lane >> 4) * 8;
    const int brow = lane & 7;
    const int bkof = ((lane >> 3) & 1) * 8;
    const int bnt  = (lane >> 4);

    auto compute_slab = [&](int buf) {
        const uint32_t ab = sb + (uint32_t)buf * STG;
        const uint32_t bb = ab + NA * ASZA;
#pragma unroll
        for (int kk = 0; kk < KSLAB; kk += 16) {
            uint32_t a_h[MT][4], a_l[MT][4];
#pragma unroll
            for (int mt = 0; mt < MT; mt++) {
                const uint32_t ao = ab +
                    (uint32_t)((wm * (BM / WM) + mt * 16 + arow) * RSTRB +
                               (kk + akof) * 2);
                ldsm4(a_h[mt], ao);
                if (SPLITA) ldsm4(a_l[mt], ao + ASZA);
            }
#pragma unroll
            for (int np = 0; np < NT8 / 2; np++) {
                const uint32_t bo = bb +
                    (uint32_t)((wn * (BN / WN) + np * 16 + bnt * 8 + brow) * RSTRB +
                               (kk + bkof) * 2);
                uint32_t th[4], tl[4];
                ldsm4(th, bo);
                if (SPLITB) ldsm4(tl, bo + ASZB);
                uint32_t bh0[2] = {th[0], th[1]}, bh1[2] = {th[2], th[3]};
                // product-outer: independent HMMAs between same-acc reuses
#pragma unroll
                for (int mt = 0; mt < MT; mt++) {
                    hmma<FMT>(acc[mt][np * 2],     a_h[mt], bh0);
                    hmma<FMT>(acc[mt][np * 2 + 1], a_h[mt], bh1);
                }
                if (SPLITB) {
                    uint32_t bl0[2] = {tl[0], tl[1]}, bl1[2] = {tl[2], tl[3]};
#pragma unroll
                    for (int mt = 0; mt < MT; mt++) {
                        hmma<FMT>(acc[mt][np * 2],     a_h[mt], bl0);
                        hmma<FMT>(acc[mt][np * 2 + 1], a_h[mt], bl1);
                    }
                }
                if (SPLITA) {
#pragma unroll
                    for (int mt = 0; mt < MT; mt++) {
                        hmma<FMT>(acc[mt][np * 2],     a_l[mt], bh0);
                        hmma<FMT>(acc[mt][np * 2 + 1], a_l[mt], bh1);
                    }
                }
            }
        }
    };

    const int NS = K / KSLAB;

    if (STAGES == 2) {
        load_slab(0, 0);
        cp_commit();
        for (int s = 0; s < NS; s++) {
            const int buf = s & 1;
            if (s + 1 < NS) { load_slab(s + 1, buf ^ 1); cp_commit(); cp_wait<1>(); }
            else            { cp_wait<0>(); }
            __syncthreads();
            compute_slab(buf);
            __syncthreads();
        }
    } else {  // STAGES == 3, single sync per iteration
        load_slab(0, 0);
        cp_commit();
        if (NS > 1) { load_slab(1, 1); cp_commit(); }
        for (int s = 0; s < NS; s++) {
            if (s + 1 < NS) cp_wait<1>();
            else            cp_wait<0>();
            __syncthreads();
            if (s + 2 < NS) { load_slab(s + 2, (s + 2) % 3); cp_commit(); }
            compute_slab(s % 3);
        }
        __syncthreads();   // protect smem reuse in staged epilogue
    }

    // ---- epilogue ----
    const int mrow = lane >> 2;
    const int ncol = (lane & 3) * 2;

    if (EPI == 2) {
        // stage fp32 tile through smem as [n][m], then coalesced float4 rows
        float* sf = (float*)smem;
#pragma unroll
        for (int mt = 0; mt < MT; mt++)
#pragma unroll
            for (int nt = 0; nt < NT8; nt++) {
                const int ml = wm * (BM / WM) + mt * 16 + mrow;
                const int nl = wn * (BN / WN) + nt * 8 + ncol;
                const float* c = acc[mt][nt];
                sf[nl * (BM + 4) + ml]           = c[0];
                sf[(nl + 1) * (BM + 4) + ml]     = c[1];
                sf[nl * (BM + 4) + ml + 8]       = c[2];
                sf[(nl + 1) * (BM + 4) + ml + 8] = c[3];
            }
        __syncthreads();
#pragma unroll
        for (int j = 0; j < BM * BN / (THREADS * 4); j++) {
            const int fid = tid + j * THREADS;
            const int nl = fid / (BM / 4);
            const int m4 = (fid % (BM / 4)) * 4;
            float4 v = *(const float4*)&sf[nl * (BM + 4) + m4];
            *(float4*)&Cf[(long long)(n0 + nl) * ldC + m0 + m4] = v;
        }
        return;
    }

#pragma unroll
    for (int mt = 0; mt < MT; mt++)
#pragma unroll
        for (int nt = 0; nt < NT8; nt++) {
            const int m = m0 + wm * (BM / WM) + mt * 16 + mrow;
            const int n = n0 + wn * (BN / WN) + nt * 8 + ncol;
            const float* c = acc[mt][nt];
            if (EPI == 0) {
                *(float2*)&Cf[(long long)m * ldC + n]       = make_float2(c[0], c[1]);
                *(float2*)&Cf[(long long)(m + 8) * ldC + n] = make_float2(c[2], c[3]);
            } else {
                const float b0 = bias[n], b1 = bias[n + 1];
                __nv_bfloat16 h0, h1, h2, h3, l0, l1, l2, l3;
                split2(c[0] + b0, h0, l0); split2(c[1] + b1, h1, l1);
                split2(c[2] + b0, h2, l2); split2(c[3] + b1, h3, l3);
                *(__nv_bfloat162*)&Chi[(long long)m * ldC + n]       = __halves2bfloat162(h0, h1);
                *(__nv_bfloat162*)&Clo[(long long)m * ldC + n]       = __halves2bfloat162(l0, l1);
                *(__nv_bfloat162*)&Chi[(long long)(m + 8) * ldC + n] = __halves2bfloat162(h2, h3);
                *(__nv_bfloat162*)&Clo[(long long)(m + 8) * ldC + n] = __halves2bfloat162(l2, l3);
            }
        }
}

// ---------------------------------------------------------------------------
// Launch: prep, proj on default stream, then 4 per-batch branches
// (energy_b -> softmax_b -> out_b) forked across streams and joined back.
// ---------------------------------------------------------------------------
extern "C" void kernel_launch(void* const* d_in, const int* in_sizes, int n_in,
                              void* d_out, int out_size)
{
    (void)in_sizes; (void)n_in; (void)out_size;
    const float* p  = (const float*)d_in[0];
    const float* bt = (const float*)d_in[1];
    const float* Wq = (const float*)d_in[2];
    const float* bq = (const float*)d_in[3];
    const float* Wk = (const float*)d_in[4];
    const float* bk = (const float*)d_in[5];
    float* out = (float*)d_out;

    auto sym = [](const void* s) { void* a; cudaGetSymbolAddress(&a, s); return a; };
    __nv_bfloat16* x_hi  = (__nv_bfloat16*)sym(g_x_hi);
    __nv_bfloat16* x_lo  = (__nv_bfloat16*)sym(g_x_lo);
    __nv_bfloat16* w_hi  = (__nv_bfloat16*)sym(g_w_hi);
    __nv_bfloat16* w_lo  = (__nv_bfloat16*)sym(g_w_lo);
    float*         bias2 = (float*)sym(g_bias2);
    __nv_bfloat16* qk_hi = (__nv_bfloat16*)sym(g_qk_hi);
    __nv_bfloat16* qk_lo = (__nv_bfloat16*)sym(g_qk_lo);
    float*         att   = (float*)sym(g_att);
    __half*        ph    = (__half*)sym(g_ph);
    __half*        vh    = (__half*)sym(g_vh);

    const long long QKOFF = (long long)BATCH * NTOK * COUT;  // k region offset
    const long long NN    = (long long)NTOK * NTOK;
    const long long CN    = (long long)CIN * NTOK;
    const long long NO    = (long long)NTOK * COUT;

    // smem sizing: max(pipeline, EPI2 epilogue tile)
    constexpr int SM_PRJ = 2 * (2 * 128 * RSTRB + 2 * 128 * RSTRB);     // 81920
    constexpr int SM_ENE = SM_PRJ;                                      // 81920
    constexpr int STG_OUT = 1 * 128 * RSTRB + 1 * 256 * RSTRB;          // 30720
    constexpr int EPI2_TILE = (128 + 4) * 256 * 4;                      // 135168
    constexpr int SM_OUT = (3 * STG_OUT > EPI2_TILE) ? 3 * STG_OUT : EPI2_TILE;
    static_assert(SM_OUT >= 3 * STG_OUT && SM_OUT >= EPI2_TILE, "smem sizing");

    cudaFuncSetAttribute((const void*)gemm_mma<0, 128, 128, 2, 4, true, true, 1, 2, 2, 4>,
                         cudaFuncAttributeMaxDynamicSharedMemorySize, SM_PRJ);
    cudaFuncSetAttribute((const void*)gemm_mma<0, 128, 128, 2, 4, true, true, 0, 2, 2, 1>,
                         cudaFuncAttributeMaxDynamicSharedMemorySize, SM_ENE);
    cudaFuncSetAttribute((const void*)gemm_mma<1, 128, 256, 2, 8, false, false, 2, 3, 1, 1>,
                         cudaFuncAttributeMaxDynamicSharedMemorySize, SM_OUT);

    // #1: fused prep (default stream)
    {
        dim3 g(NTOK / 32, CIN / 32, 2 * BATCH + 1), b(32, 8);
        prep_all<<<g, b>>>(p, bt, Wq, Wk, bq, bk,
                           x_hi, x_lo, vh, w_hi, w_lo, bias2);
    }

    // #2: merged projections q|k (default stream)
    {
        dim3 g(NTOK / 128, 1, 2 * BATCH);
        gemm_mma<0, 128, 128, 2, 4, true, true, 1, 2, 2, 4><<<g, 256, SM_PRJ>>>(
            (const uint16_t*)x_hi, (const uint16_t*)x_lo,
            (const uint16_t*)w_hi, (const uint16_t*)w_lo,
            bias2, nullptr, qk_hi, qk_lo,
            CIN, (long long)NTOK * CIN, (long long)COUT * CIN, NO, COUT);
    }

    const bool fork = g_ss.ok;
    if (fork) {
        cudaEventRecord(g_ss.root, 0);
        for (int i = 0; i < BATCH - 1; i++)
            cudaStreamWaitEvent(g_ss.s[i], g_ss.root, 0);
    }

    // Per-batch branches: energy_b -> softmax_b -> out_b.
    dim3 gE(NTOK / 128, NTOK / 128, 1);
    dim3 gO(NTOK / 128, CIN / 256, 1);   // single c-tile: P read once
    for (int b = 0; b < BATCH; b++) {
        cudaStream_t st = (fork && b > 0) ? g_ss.s[b - 1] : (cudaStream_t)0;
        gemm_mma<0, 128, 128, 2, 4, true, true, 0, 2, 2, 1><<<gE, 256, SM_ENE, st>>>(
            (const uint16_t*)(qk_hi + (long long)b * NO),
            (const uint16_t*)(qk_lo + (long long)b * NO),
            (const uint16_t*)(qk_hi + QKOFF + (long long)b * NO),
            (const uint16_t*)(qk_lo + QKOFF + (long long)b * NO),
            nullptr, att + (long long)b * NN, nullptr, nullptr,
            COUT, 0LL, 0LL, 0LL, NTOK);
    }
    for (int b = 0; b < BATCH; b++) {
        cudaStream_t st = (fork && b > 0) ? g_ss.s[b - 1] : (cudaStream_t)0;
        softmax_fp16<<<NTOK, 256, 0, st>>>(att + (long long)b * NN,
                                           ph + (long long)b * NN);
        gemm_mma<1, 128, 256, 2, 8, false, false, 2, 3, 1, 1><<<gO, 512, SM_OUT, st>>>(
            (const uint16_t*)(ph + (long long)b * NN), nullptr,
            (const uint16_t*)(vh + (long long)b * CN), nullptr,
            nullptr, out + (long long)b * CN, nullptr, nullptr,
            NTOK, 0LL, 0LL, 0LL, NTOK);
    }

    if (fork) {
        for (int i = 0; i < BATCH - 1; i++) {
            cudaEventRecord(g_ss.done[i], g_ss.s[i]);
            cudaStreamWaitEvent((cudaStream_t)0, g_ss.done[i], 0);
        }
    }
}

// round 14
// speedup vs baseline: 1.0479x; 1.0479x over previous
#include <cuda_runtime.h>
#include <cuda_bf16.h>
#include <cuda_fp16.h>
#include <cstdint>

#define BATCH 4
#define CIN   256
#define COUT  128
#define NTOK  4096

// ---------------------------------------------------------------------------
// Scratch (__device__ globals; allocation-free rule)
// Packed layouts so one GEMM launch covers q AND k:
//   g_x_*  : z in [0,4) = p^T [b][n][c], z in [4,8) = b^T [b][n][c]
//   g_w_*  : [0,COUT*CIN) = Wq, [COUT*CIN, 2*COUT*CIN) = Wk
//   g_bias2: [0,COUT) = bq, [COUT,2*COUT) = bk
//   g_qk_* : z in [0,4) = q [b][n][o], z in [4,8) = k [b][m][o]
// ---------------------------------------------------------------------------
__device__ __nv_bfloat16 g_x_hi [(long long)2 * BATCH * NTOK * CIN];
__device__ __nv_bfloat16 g_x_lo [(long long)2 * BATCH * NTOK * CIN];
__device__ __nv_bfloat16 g_w_hi [2 * COUT * CIN];
__device__ __nv_bfloat16 g_w_lo [2 * COUT * CIN];
__device__ float         g_bias2[2 * COUT];
__device__ __nv_bfloat16 g_qk_hi[(long long)2 * BATCH * NTOK * COUT];
__device__ __nv_bfloat16 g_qk_lo[(long long)2 * BATCH * NTOK * COUT];
__device__ float         g_att  [(long long)BATCH * NTOK * NTOK];   // fp32 logits
__device__ __half        g_ph   [(long long)BATCH * NTOK * NTOK];   // softmax fp16
__device__ __half        g_vh   [(long long)BATCH * CIN * NTOK];    // V fp16 [b][c][m]

// ---------------------------------------------------------------------------
// Streams/events for per-batch pipeline overlap (created in static init;
// fork/join via events is stream-capture legal).
// ---------------------------------------------------------------------------
struct GpuSideStreams {
    cudaStream_t s[BATCH - 1];
    cudaEvent_t  root;
    cudaEvent_t  done[BATCH - 1];
    bool ok;
    GpuSideStreams() : ok(true) {
        for (int i = 0; i < BATCH - 1; i++)
            ok &= (cudaStreamCreateWithFlags(&s[i], cudaStreamNonBlocking) == cudaSuccess);
        ok &= (cudaEventCreateWithFlags(&root, cudaEventDisableTiming) == cudaSuccess);
        for (int i = 0; i < BATCH - 1; i++)
            ok &= (cudaEventCreateWithFlags(&done[i], cudaEventDisableTiming) == cudaSuccess);
    }
};
static GpuSideStreams g_ss;

// ---------------------------------------------------------------------------
// Helpers (plain sm_80+ PTX; toolchain targets compute_103 — no tcgen05)
// ---------------------------------------------------------------------------
__device__ __forceinline__ uint32_t smem_u32(const void* p) {
    uint32_t a;
    asm("{ .reg .u64 t; cvta.to.shared.u64 t, %1; cvt.u32.u64 %0, t; }"
        : "=r"(a) : "l"(p));
    return a;
}
__device__ __forceinline__ void cp16(uint32_t dst, const void* src) {
    asm volatile("cp.async.cg.shared.global [%0], [%1], 16;"
                 :: "r"(dst), "l"(src) : "memory");
}
__device__ __forceinline__ void cp_commit() {
    asm volatile("cp.async.commit_group;" ::: "memory");
}
template<int N>
__device__ __forceinline__ void cp_wait() {
    asm volatile("cp.async.wait_group %0;" :: "n"(N) : "memory");
}
__device__ __forceinline__ void ldsm4(uint32_t* r, uint32_t addr) {
    asm volatile("ldmatrix.sync.aligned.m8n8.x4.shared.b16 {%0,%1,%2,%3}, [%4];"
                 : "=r"(r[0]), "=r"(r[1]), "=r"(r[2]), "=r"(r[3]) : "r"(addr));
}
// FMT 0 = bf16, FMT 1 = fp16 (same fragment layout, different instruction)
template<int FMT>
__device__ __forceinline__ void hmma(float* c, const uint32_t* a, const uint32_t* b) {
    if (FMT == 0)
        asm volatile(
            "mma.sync.aligned.m16n8k16.row.col.f32.bf16.bf16.f32 "
            "{%0,%1,%2,%3}, {%4,%5,%6,%7}, {%8,%9}, {%0,%1,%2,%3};"
            : "+f"(c[0]), "+f"(c[1]), "+f"(c[2]), "+f"(c[3])
            : "r"(a[0]), "r"(a[1]), "r"(a[2]), "r"(a[3]), "r"(b[0]), "r"(b[1]));
    else
        asm volatile(
            "mma.sync.aligned.m16n8k16.row.col.f32.f16.f16.f32 "
            "{%0,%1,%2,%3}, {%4,%5,%6,%7}, {%8,%9}, {%0,%1,%2,%3};"
            : "+f"(c[0]), "+f"(c[1]), "+f"(c[2]), "+f"(c[3])
            : "r"(a[0]), "r"(a[1]), "r"(a[2]), "r"(a[3]), "r"(b[0]), "r"(b[1]));
}
__device__ __forceinline__ void split2(float x, __nv_bfloat16& h, __nv_bfloat16& l) {
    h = __float2bfloat16(x);
    l = __float2bfloat16(x - __bfloat162float(h));
}

// ---------------------------------------------------------------------------
// Fused prep (single launch):
//  z in [0,BATCH):        p [c][n] -> x hi/lo [z][n][c] (bf16)
//  z in [BATCH,2*BATCH):  b [c][n] -> x hi/lo [z][n][c] (bf16) AND V fp16 [c][n]
//  z == 2*BATCH:          Wq|Wk elementwise bf16 split + bias pack
// ---------------------------------------------------------------------------
__global__ __launch_bounds__(256)
void prep_all(const float* __restrict__ p, const float* __restrict__ bsrc,
              const float* __restrict__ Wq, const float* __restrict__ Wk,
              const float* __restrict__ bq, const float* __restrict__ bk,
              __nv_bfloat16* __restrict__ x_hi, __nv_bfloat16* __restrict__ x_lo,
              __half* __restrict__ vh,
              __nv_bfloat16* __restrict__ w_hi, __nv_bfloat16* __restrict__ w_lo,
              float* __restrict__ bias2)
{
    const int z = blockIdx.z;
    const int tx = threadIdx.x, ty = threadIdx.y;
    const int tid = ty * 32 + tx;

    if (z == 2 * BATCH) {
        int idx = (blockIdx.y * gridDim.x + blockIdx.x) * 256 + tid;
        if (idx < 2 * COUT * CIN) {
            float v = (idx < COUT * CIN) ? Wq[idx] : Wk[idx - COUT * CIN];
            split2(v, w_hi[idx], w_lo[idx]);
        }
        if (blockIdx.x == 0 && blockIdx.y == 0)
            bias2[tid] = (tid < COUT) ? bq[tid] : bk[tid - COUT];
        return;
    }

    const bool isB = (z >= BATCH);
    const int  zb  = isB ? z - BATCH : z;
    const float* in = isB ? bsrc : p;

    __shared__ float t[32][33];
    const long long zin  = (long long)zb * CIN * NTOK;
    const long long zout = (long long)z  * NTOK * CIN;
    const int n0 = blockIdx.x * 32, c0 = blockIdx.y * 32;

#pragma unroll
    for (int j = 0; j < 32; j += 8) {
        const long long src = zin + (long long)(c0 + ty + j) * NTOK + n0 + tx;
        float v = in[src];
        t[ty + j][tx] = v;
        if (isB) vh[src] = __float2half_rn(v);
    }
    __syncthreads();
#pragma unroll
    for (int j = 0; j < 32; j += 8) {
        float v = t[tx][ty + j];
        __nv_bfloat16 h, l;
        split2(v, h, l);
        long long o = zout + (long long)(n0 + ty + j) * CIN + c0 + tx;
        x_hi[o] = h; x_lo[o] = l;
    }
}

// ---------------------------------------------------------------------------
// Softmax over rows of att; writes single fp16 probs
// ---------------------------------------------------------------------------
__device__ __forceinline__ float warp_max(float x) {
#pragma unroll
    for (int o = 16; o > 0; o >>= 1) x = fmaxf(x, __shfl_xor_sync(0xffffffffu, x, o));
    return x;
}
__device__ __forceinline__ float warp_sum(float x) {
#pragma unroll
    for (int o = 16; o > 0; o >>= 1) x += __shfl_xor_sync(0xffffffffu, x, o);
    return x;
}

__global__ __launch_bounds__(256)
void softmax_fp16(const float* __restrict__ att, __half* __restrict__ ph) {
    const long long ro = (long long)blockIdx.x * NTOK;
    const float* row = att + ro;
    const int tid = threadIdx.x;

    float4 v[4];
    float m = -1e30f;
#pragma unroll
    for (int i = 0; i < 4; i++) {
        v[i] = *(const float4*)(row + i * 1024 + tid * 4);
        m = fmaxf(m, fmaxf(fmaxf(v[i].x, v[i].y), fmaxf(v[i].z, v[i].w)));
    }
    __shared__ float sred[8];
    m = warp_max(m);
    if ((tid & 31) == 0) sred[tid >> 5] = m;
    __syncthreads();
    {
        float t = (tid < 8) ? sred[tid & 7] : -1e30f;
        t = warp_max(t);
        if (tid == 0) sred[0] = t;
    }
    __syncthreads();
    m = sred[0];

    float s = 0.f;
#pragma unroll
    for (int i = 0; i < 4; i++) {
        v[i].x = __expf(v[i].x - m); v[i].y = __expf(v[i].y - m);
        v[i].z = __expf(v[i].z - m); v[i].w = __expf(v[i].w - m);
        s += v[i].x + v[i].y + v[i].z + v[i].w;
    }
    s = warp_sum(s);
    __syncthreads();
    if ((tid & 31) == 0) sred[tid >> 5] = s;
    __syncthreads();
    {
        float t = (tid < 8) ? sred[tid & 7] : 0.f;
        t = warp_sum(t);
        if (tid == 0) sred[0] = t;
    }
    __syncthreads();
    const float inv = 1.f / sred[0];

#pragma unroll
    for (int i = 0; i < 4; i++) {
        long long off = ro + i * 1024 + tid * 4;
        ((__half2*)(ph + off))[0] =
            __floats2half2_rn(v[i].x * inv, v[i].y * inv);
        ((__half2*)(ph + off))[1] =
            __floats2half2_rn(v[i].z * inv, v[i].w * inv);
    }
}

// ---------------------------------------------------------------------------
// Split-precision HMMA GEMM:  C[m][n] = sum_k A(m,k)*B(n,k), A/B K-major.
// Products: ah*bh  (+ ah*bl if SPLITB)  (+ al*bh if SPLITA)
// OCC   = min blocks/SM for launch_bounds
// ZDIVB = B (and bias) advance by z/ZDIVB (one launch covers Wq and Wk)
// STAGES: 2 = classic two-sync double buffer; >=3 = single-sync ring
//         (ring requires K/KSLAB >= STAGES).
// EPI 0: Cf[m*ldC + n] fp32   EPI 1: Chi/Clo +bias   EPI 2: Cf[n*ldC+m] staged
// NOTE: dynamic smem must be >= max(STAGES*STG, EPI2 tile (BM+4)*BN*4).
// ---------------------------------------------------------------------------
#define KSLAB 32
#define RSTRB 80   // smem row stride bytes (32 elems + 16B pad, conflict-free)

template<int FMT, int BM, int BN, int WM, int WN, bool SPLITA, bool SPLITB,
         int EPI, int STAGES, int OCC, int ZDIVB>
__global__ __launch_bounds__(WM * WN * 32, OCC)
void gemm_mma(const uint16_t* __restrict__ Ah, const uint16_t* __restrict__ Al,
              const uint16_t* __restrict__ Bh, const uint16_t* __restrict__ Bl,
              const float* __restrict__ bias,
              float* __restrict__ Cf,
              __nv_bfloat16* __restrict__ Chi, __nv_bfloat16* __restrict__ Clo,
              int K, long long sA, long long sB, long long sC, int ldC)
{
    constexpr int THREADS = WM * WN * 32;
    constexpr int MT   = BM / WM / 16;
    constexpr int NT8  = BN / WN / 8;
    constexpr int ASZA = BM * RSTRB;
    constexpr int ASZB = BN * RSTRB;
    constexpr int NA   = SPLITA ? 2 : 1;
    constexpr int NB   = SPLITB ? 2 : 1;
    constexpr int STG  = NA * ASZA + NB * ASZB;

    extern __shared__ char smem[];
    const uint32_t sb = smem_u32(smem);
    const int tid = threadIdx.x, warp = tid >> 5, lane = tid & 31;
    const int wm = warp % WM, wn = warp / WM;
    const int m0 = blockIdx.x * BM;
    const int n0 = blockIdx.y * BN;
    const int z  = blockIdx.z;
    const int zb = z / ZDIVB;

    Ah += (long long)z * sA + (long long)m0 * K;
    if (SPLITA) Al += (long long)z * sA + (long long)m0 * K;
    Bh += (long long)zb * sB + (long long)n0 * K;
    if (SPLITB) Bl += (long long)zb * sB + (long long)n0 * K;
    if (EPI == 0 || EPI == 2) Cf += (long long)z * sC;
    else { Chi += (long long)z * sC; Clo += (long long)z * sC; bias += (long long)zb * ldC; }

    float acc[MT][NT8][4];
#pragma unroll
    for (int i = 0; i < MT; i++)
#pragma unroll
        for (int j = 0; j < NT8; j++)
#pragma unroll
            for (int r = 0; r < 4; r++) acc[i][j][r] = 0.f;

    auto load_slab = [&](int s, int b) {
        const uint32_t base = sb + (uint32_t)b * STG;
        const long long kof = (long long)s * KSLAB;
#pragma unroll
        for (int i = 0; i < BM * 4 / THREADS; i++) {
            const int id = tid + i * THREADS;
            const int r = id >> 2, g = id & 3;
            const uint32_t so = base + (uint32_t)(r * RSTRB + g * 16);
            const long long go = (long long)r * K + kof + g * 8;
            cp16(so, Ah + go);
            if (SPLITA) cp16(so + ASZA, Al + go);
        }
        const uint32_t bbase = base + NA * ASZA;
#pragma unroll
        for (int i = 0; i < BN * 4 / THREADS; i++) {
            const int id = tid + i * THREADS;
            const int r = id >> 2, g = id & 3;
            const uint32_t so = bbase + (uint32_t)(r * RSTRB + g * 16);
            const long long go = (long long)r * K + kof + g * 8;
            cp16(so, Bh + go);
            if (SPLITB) cp16(so + ASZB, Bl + go);
        }
    };

    const int arow = (lane & 7) + ((lane >> 3) & 1) * 8;
    const int akof = (lane >> 4) * 8;
    const int brow = lane & 7;
    const int bkof = ((lane >> 3) & 1) * 8;
    const int bnt  = (lane >> 4);

    auto compute_slab = [&](int buf) {
        const uint32_t ab = sb + (uint32_t)buf * STG;
        const uint32_t bb = ab + NA * ASZA;
#pragma unroll
        for (int kk = 0; kk < KSLAB; kk += 16) {
            uint32_t a_h[MT][4], a_l[MT][4];
#pragma unroll
            for (int mt = 0; mt < MT; mt++) {
                const uint32_t ao = ab +
                    (uint32_t)((wm * (BM / WM) + mt * 16 + arow) * RSTRB +
                               (kk + akof) * 2);
                ldsm4(a_h[mt], ao);
                if (SPLITA) ldsm4(a_l[mt], ao + ASZA);
            }
#pragma unroll
            for (int np = 0; np < NT8 / 2; np++) {
                const uint32_t bo = bb +
                    (uint32_t)((wn * (BN / WN) + np * 16 + bnt * 8 + brow) * RSTRB +
                               (kk + bkof) * 2);
                uint32_t th[4], tl[4];
                ldsm4(th, bo);
                if (SPLITB) ldsm4(tl, bo + ASZB);
                uint32_t bh0[2] = {th[0], th[1]}, bh1[2] = {th[2], th[3]};
                // product-outer: independent HMMAs between same-acc reuses
#pragma unroll
                for (int mt = 0; mt < MT; mt++) {
                    hmma<FMT>(acc[mt][np * 2],     a_h[mt], bh0);
                    hmma<FMT>(acc[mt][np * 2 + 1], a_h[mt], bh1);
                }
                if (SPLITB) {
                    uint32_t bl0[2] = {tl[0], tl[1]}, bl1[2] = {tl[2], tl[3]};
#pragma unroll
                    for (int mt = 0; mt < MT; mt++) {
                        hmma<FMT>(acc[mt][np * 2],     a_h[mt], bl0);
                        hmma<FMT>(acc[mt][np * 2 + 1], a_h[mt], bl1);
                    }
                }
                if (SPLITA) {
#pragma unroll
                    for (int mt = 0; mt < MT; mt++) {
                        hmma<FMT>(acc[mt][np * 2],     a_l[mt], bh0);
                        hmma<FMT>(acc[mt][np * 2 + 1], a_l[mt], bh1);
                    }
                }
            }
        }
    };

    const int NS = K / KSLAB;

    if (STAGES == 2) {
        load_slab(0, 0);
        cp_commit();
        for (int s = 0; s < NS; s++) {
            const int buf = s & 1;
            if (s + 1 < NS) { load_slab(s + 1, buf ^ 1); cp_commit(); cp_wait<1>(); }
            else            { cp_wait<0>(); }
            __syncthreads();
            compute_slab(buf);
            __syncthreads();
        }
    } else {
        // Generic single-sync ring (STAGES >= 3; requires NS >= STAGES).
        for (int i = 0; i < STAGES - 1; i++) { load_slab(i, i); cp_commit(); }
        for (int s = 0; s < NS; s++) {
            cp_wait<STAGES - 2>();     // slab s landed
            __syncthreads();           // also protects buffer about to be refilled
            if (s + STAGES - 1 < NS) { load_slab(s + STAGES - 1, (s + STAGES - 1) % STAGES); cp_commit(); }
            compute_slab(s % STAGES);
        }
        __syncthreads();   // protect smem reuse in staged epilogue
    }

    // ---- epilogue ----
    const int mrow = lane >> 2;
    const int ncol = (lane & 3) * 2;

    if (EPI == 2) {
        // stage fp32 tile through smem as [n][m], then coalesced float4 rows
        float* sf = (float*)smem;
#pragma unroll
        for (int mt = 0; mt < MT; mt++)
#pragma unroll
            for (int nt = 0; nt < NT8; nt++) {
                const int ml = wm * (BM / WM) + mt * 16 + mrow;
                const int nl = wn * (BN / WN) + nt * 8 + ncol;
                const float* c = acc[mt][nt];
                sf[nl * (BM + 4) + ml]           = c[0];
                sf[(nl + 1) * (BM + 4) + ml]     = c[1];
                sf[nl * (BM + 4) + ml + 8]       = c[2];
                sf[(nl + 1) * (BM + 4) + ml + 8] = c[3];
            }
        __syncthreads();
#pragma unroll
        for (int j = 0; j < BM * BN / (THREADS * 4); j++) {
            const int fid = tid + j * THREADS;
            const int nl = fid / (BM / 4);
            const int m4 = (fid % (BM / 4)) * 4;
            float4 v = *(const float4*)&sf[nl * (BM + 4) + m4];
            *(float4*)&Cf[(long long)(n0 + nl) * ldC + m0 + m4] = v;
        }
        return;
    }

#pragma unroll
    for (int mt = 0; mt < MT; mt++)
#pragma unroll
        for (int nt = 0; nt < NT8; nt++) {
            const int m = m0 + wm * (BM / WM) + mt * 16 + mrow;
            const int n = n0 + wn * (BN / WN) + nt * 8 + ncol;
            const float* c = acc[mt][nt];
            if (EPI == 0) {
                *(float2*)&Cf[(long long)m * ldC + n]       = make_float2(c[0], c[1]);
                *(float2*)&Cf[(long long)(m + 8) * ldC + n] = make_float2(c[2], c[3]);
            } else {
                const float b0 = bias[n], b1 = bias[n + 1];
                __nv_bfloat16 h0, h1, h2, h3, l0, l1, l2, l3;
                split2(c[0] + b0, h0, l0); split2(c[1] + b1, h1, l1);
                split2(c[2] + b0, h2, l2); split2(c[3] + b1, h3, l3);
                *(__nv_bfloat162*)&Chi[(long long)m * ldC + n]       = __halves2bfloat162(h0, h1);
                *(__nv_bfloat162*)&Clo[(long long)m * ldC + n]       = __halves2bfloat162(l0, l1);
                *(__nv_bfloat162*)&Chi[(long long)(m + 8) * ldC + n] = __halves2bfloat162(h2, h3);
                *(__nv_bfloat162*)&Clo[(long long)(m + 8) * ldC + n] = __halves2bfloat162(l2, l3);
            }
        }
}

// ---------------------------------------------------------------------------
// Launch: prep, proj on default stream, then 4 per-batch branches
// (energy_b -> softmax_b -> out_b) forked across streams and joined back.
// ---------------------------------------------------------------------------
extern "C" void kernel_launch(void* const* d_in, const int* in_sizes, int n_in,
                              void* d_out, int out_size)
{
    (void)in_sizes; (void)n_in; (void)out_size;
    const float* p  = (const float*)d_in[0];
    const float* bt = (const float*)d_in[1];
    const float* Wq = (const float*)d_in[2];
    const float* bq = (const float*)d_in[3];
    const float* Wk = (const float*)d_in[4];
    const float* bk = (const float*)d_in[5];
    float* out = (float*)d_out;

    auto sym = [](const void* s) { void* a; cudaGetSymbolAddress(&a, s); return a; };
    __nv_bfloat16* x_hi  = (__nv_bfloat16*)sym(g_x_hi);
    __nv_bfloat16* x_lo  = (__nv_bfloat16*)sym(g_x_lo);
    __nv_bfloat16* w_hi  = (__nv_bfloat16*)sym(g_w_hi);
    __nv_bfloat16* w_lo  = (__nv_bfloat16*)sym(g_w_lo);
    float*         bias2 = (float*)sym(g_bias2);
    __nv_bfloat16* qk_hi = (__nv_bfloat16*)sym(g_qk_hi);
    __nv_bfloat16* qk_lo = (__nv_bfloat16*)sym(g_qk_lo);
    float*         att   = (float*)sym(g_att);
    __half*        ph    = (__half*)sym(g_ph);
    __half*        vh    = (__half*)sym(g_vh);

    const long long QKOFF = (long long)BATCH * NTOK * COUT;  // k region offset
    const long long NN    = (long long)NTOK * NTOK;
    const long long CN    = (long long)CIN * NTOK;
    const long long NO    = (long long)NTOK * COUT;

    // smem sizing: max(pipeline, EPI2 epilogue tile) — R12-proven configs,
    // out pipeline deepened to 4 stages.
    constexpr int SM_PRJ = 2 * (2 * 128 * RSTRB + 2 * 128 * RSTRB);     // 81920
    constexpr int SM_ENE = SM_PRJ;                                      // 81920
    constexpr int STG_OUT = 1 * 128 * RSTRB + 1 * 128 * RSTRB;          // 20480
    constexpr int EPI2_TILE = (128 + 4) * 128 * 4;                      // 67584
    constexpr int SM_OUT = (4 * STG_OUT > EPI2_TILE) ? 4 * STG_OUT : EPI2_TILE;
    static_assert(SM_OUT >= 4 * STG_OUT && SM_OUT >= EPI2_TILE, "smem sizing");

    cudaFuncSetAttribute((const void*)gemm_mma<0, 128, 128, 2, 4, true, true, 1, 2, 2, 4>,
                         cudaFuncAttributeMaxDynamicSharedMemorySize, SM_PRJ);
    cudaFuncSetAttribute((const void*)gemm_mma<0, 128, 128, 2, 4, true, true, 0, 2, 2, 1>,
                         cudaFuncAttributeMaxDynamicSharedMemorySize, SM_ENE);
    cudaFuncSetAttribute((const void*)gemm_mma<1, 128, 128, 2, 4, false, false, 2, 4, 2, 1>,
                         cudaFuncAttributeMaxDynamicSharedMemorySize, SM_OUT);

    // #1: fused prep (default stream)
    {
        dim3 g(NTOK / 32, CIN / 32, 2 * BATCH + 1), b(32, 8);
        prep_all<<<g, b>>>(p, bt, Wq, Wk, bq, bk,
                           x_hi, x_lo, vh, w_hi, w_lo, bias2);
    }

    // #2: merged projections q|k (default stream)
    {
        dim3 g(NTOK / 128, 1, 2 * BATCH);
        gemm_mma<0, 128, 128, 2, 4, true, true, 1, 2, 2, 4><<<g, 256, SM_PRJ>>>(
            (const uint16_t*)x_hi, (const uint16_t*)x_lo,
            (const uint16_t*)w_hi, (const uint16_t*)w_lo,
            bias2, nullptr, qk_hi, qk_lo,
            CIN, (long long)NTOK * CIN, (long long)COUT * CIN, NO, COUT);
    }

    const bool fork = g_ss.ok;
    if (fork) {
        cudaEventRecord(g_ss.root, 0);
        for (int i = 0; i < BATCH - 1; i++)
            cudaStreamWaitEvent(g_ss.s[i], g_ss.root, 0);
    }

    // Per-batch branches: energy_b -> softmax_b -> out_b.
    dim3 gE(NTOK / 128, NTOK / 128, 1);
    dim3 gO(NTOK / 128, CIN / 128, 1);
    for (int b = 0; b < BATCH; b++) {
        cudaStream_t st = (fork && b > 0) ? g_ss.s[b - 1] : (cudaStream_t)0;
        gemm_mma<0, 128, 128, 2, 4, true, true, 0, 2, 2, 1><<<gE, 256, SM_ENE, st>>>(
            (const uint16_t*)(qk_hi + (long long)b * NO),
            (const uint16_t*)(qk_lo + (long long)b * NO),
            (const uint16_t*)(qk_hi + QKOFF + (long long)b * NO),
            (const uint16_t*)(qk_lo + QKOFF + (long long)b * NO),
            nullptr, att + (long long)b * NN, nullptr, nullptr,
            COUT, 0LL, 0LL, 0LL, NTOK);
    }
    for (int b = 0; b < BATCH; b++) {
        cudaStream_t st = (fork && b > 0) ? g_ss.s[b - 1] : (cudaStream_t)0;
        softmax_fp16<<<NTOK, 256, 0, st>>>(att + (long long)b * NN,
                                           ph + (long long)b * NN);
        gemm_mma<1, 128, 128, 2, 4, false, false, 2, 4, 2, 1><<<gO, 256, SM_OUT, st>>>(
            (const uint16_t*)(ph + (long long)b * NN), nullptr,
            (const uint16_t*)(vh + (long long)b * CN), nullptr,
            nullptr, out + (long long)b * CN, nullptr, nullptr,
            NTOK, 0LL, 0LL, 0LL, NTOK);
    }

    if (fork) {
        for (int i = 0; i < BATCH - 1; i++) {
            cudaEventRecord(g_ss.done[i], g_ss.s[i]);
            cudaStreamWaitEvent((cudaStream_t)0, g_ss.done[i], 0);
        }
    }
}